// round 13
// baseline (speedup 1.0000x reference)
#include <cuda_runtime.h>
#include <cstdint>
#include <string.h>
#include <math.h>

#define NW 2048
#define TCN 12
#define TSN 4

// ---------------- scratch (device globals; no allocation) ----------------
__device__ float g_Xc[TCN * NW * 64];
__device__ float g_Xs[TSN * NW * 64];
__device__ float g_preC[TCN * NW * 1024];      // [t][w][dir*512+gaterow]
__device__ float g_preS[TSN * NW * 1024];
__device__ float g_outC[TCN * NW * 256];       // [t][w][256]
__device__ float g_outS[TSN * NW * 256];
__device__ float g_energy[TCN * NW * 256];
__device__ float g_e[TCN * NW];
__device__ float g_feat[NW * 768];             // [w][word|char_ctx|syl_ctx]
__device__ float g_preW[NW * 1024];
__device__ float g_y[NW * 256];

__device__ __forceinline__ float fsig(float x) {
    return __fdividef(1.f, 1.f + __expf(-x));
}
__device__ __forceinline__ float ftanh(float x) {
    float e = __expf(2.f * x);
    return 1.f - __fdividef(2.f, e + 1.f);
}

// packed dual-fp32 FMA (sm_100+ FFMA2; ptxas never emits it from C++ — PTX only)
__device__ __forceinline__ float2 ffma2(float2 a, float2 b, float2 c) {
    unsigned long long ua, ub, uc;
    memcpy(&ua, &a, 8); memcpy(&ub, &b, 8); memcpy(&uc, &c, 8);
    asm("fma.rn.f32x2 %0, %1, %2, %0;" : "+l"(uc) : "l"(ua), "l"(ub));
    float2 d; memcpy(&d, &uc, 8);
    return d;
}

// ---------------- embedding gathers ----------------
__global__ void gather_x(const int* __restrict__ ids, const float* __restrict__ emb,
                         float* __restrict__ X, int T) {
    int w = blockIdx.x, t = blockIdx.y, j = threadIdx.x;  // 64 threads
    X[((size_t)t * NW + w) * 64 + j] = emb[(size_t)ids[w * T + t] * 64 + j];
}

__global__ void gather_word(const int* __restrict__ wid, const float* __restrict__ embw,
                            float* __restrict__ feat) {
    int w = blockIdx.x, j = threadIdx.x;  // 256
    feat[(size_t)w * 768 + j] = embw[(size_t)wid[w] * 256 + j];
}

// ---------------- GEMM: C[M,N] = A[M,K]*B[N,K]^T + b1 + b2 (opt tanh), FFMA2 ----------------
#define GPAD 20
__global__ __launch_bounds__(256) void gemm_abT(
    const float* __restrict__ A, const float* __restrict__ B, float* __restrict__ C,
    const float* __restrict__ b1, const float* __restrict__ b2,
    int M, int N, int K, int do_tanh) {
    __shared__ float As[64 * GPAD];
    __shared__ float Bs[64 * GPAD];
    int tid = threadIdx.x;
    int m0 = blockIdx.y * 64, n0 = blockIdx.x * 64;
    int lrow = tid >> 2, lk = (tid & 3) * 4;
    int tx = tid & 15, ty = tid >> 4;
    float2 acc2[4][4];
#pragma unroll
    for (int i = 0; i < 4; i++)
#pragma unroll
        for (int j = 0; j < 4; j++) acc2[i][j] = make_float2(0.f, 0.f);

    for (int k0 = 0; k0 < K; k0 += 16) {
        float4 a4 = *(const float4*)(A + (size_t)(m0 + lrow) * K + k0 + lk);
        float4 b4 = *(const float4*)(B + (size_t)(n0 + lrow) * K + k0 + lk);
        __syncthreads();
        *(float4*)&As[lrow * GPAD + lk] = a4;
        *(float4*)&Bs[lrow * GPAD + lk] = b4;
        __syncthreads();
#pragma unroll
        for (int kq = 0; kq < 16; kq += 4) {
            float4 av[4], bv[4];
#pragma unroll
            for (int i = 0; i < 4; i++) av[i] = *(const float4*)&As[(ty + 16 * i) * GPAD + kq];
#pragma unroll
            for (int j = 0; j < 4; j++) bv[j] = *(const float4*)&Bs[(tx + 16 * j) * GPAD + kq];
#pragma unroll
            for (int i = 0; i < 4; i++)
#pragma unroll
                for (int j = 0; j < 4; j++) {
                    acc2[i][j] = ffma2(make_float2(av[i].x, av[i].y),
                                       make_float2(bv[j].x, bv[j].y), acc2[i][j]);
                    acc2[i][j] = ffma2(make_float2(av[i].z, av[i].w),
                                       make_float2(bv[j].z, bv[j].w), acc2[i][j]);
                }
        }
    }
#pragma unroll
    for (int i = 0; i < 4; i++) {
        int m = m0 + ty + 16 * i;
#pragma unroll
        for (int j = 0; j < 4; j++) {
            int n = n0 + tx + 16 * j;
            float v = acc2[i][j].x + acc2[i][j].y;
            if (b1) v += b1[n];
            if (b2) v += b2[n];
            if (do_tanh) v = ftanh(v);
            C[(size_t)m * N + n] = v;
        }
    }
}

// ---------------- fused persistent char/syl BiLSTM ----------------
#define FPAD 516
// smem floats: hs 2048 + cs 2048 + wbuf 16*516 = 12352  (49,408 B, dynamic)
__global__ __launch_bounds__(256, 2) void fused_lstm(
    const float* __restrict__ pre,   // [T][NW][1024]
    const float* __restrict__ Whh,   // [2][512][128]
    const int* __restrict__ fid, const float* __restrict__ embp,
    float* __restrict__ out_all,     // [T][NW][256]
    int T) {
    extern __shared__ float sm[];
    float* hs = sm;                  // [16][128]
    float* cs = sm + 2048;           // [16][128]
    float* wbuf = sm + 4096;         // [16][FPAD] chunk (k-major); reused for gates
    int tid = threadIdx.x;
    int d = blockIdx.y;
    int wbase = blockIdx.x * 16;
    int wg = tid >> 7;               // word group 0/1 (8 words each)
    int ct = tid & 127;              // col-thread: owns gate cols ct*4..ct*4+3
    const float* Wb = Whh + (size_t)d * 512 * 128;

    {   // init h0 = prefix embedding slice, c0 = 0
        int w = tid >> 4, u0 = (tid & 15) * 8;
        const float* hp = embp + (size_t)fid[wbase + w] * 256 + d * 128 + u0;
#pragma unroll
        for (int q = 0; q < 8; q++) { hs[w * 128 + u0 + q] = hp[q]; cs[w * 128 + u0 + q] = 0.f; }
    }

    for (int t = 0; t < T; t++) {
        int t_eff = d ? (T - 1 - t) : t;
        const float* prow = pre + ((size_t)t_eff * NW + wbase) * 1024 + d * 512;
        float2 acc2[8][2];
#pragma unroll
        for (int i = 0; i < 8; i++) {
            float4 p = *(const float4*)(prow + (size_t)(wg * 8 + i) * 1024 + ct * 4);
            acc2[i][0] = make_float2(p.x, p.y);
            acc2[i][1] = make_float2(p.z, p.w);
        }

#pragma unroll 1
        for (int k0 = 0; k0 < 128; k0 += 16) {
            __syncthreads();
#pragma unroll
            for (int it = 0; it < 8; it++) {      // stage 512x16 Whh chunk, k-major
                int e = tid + 256 * it;
                int n = e >> 2, kq = e & 3;
                float4 v = *(const float4*)(Wb + (size_t)n * 128 + k0 + kq * 4);
                wbuf[(kq * 4 + 0) * FPAD + n] = v.x;
                wbuf[(kq * 4 + 1) * FPAD + n] = v.y;
                wbuf[(kq * 4 + 2) * FPAD + n] = v.z;
                wbuf[(kq * 4 + 3) * FPAD + n] = v.w;
            }
            __syncthreads();
#pragma unroll
            for (int kq = 0; kq < 4; kq++) {
                float4 h4[8];
#pragma unroll
                for (int i = 0; i < 8; i++)
                    h4[i] = *(const float4*)&hs[(wg * 8 + i) * 128 + k0 + kq * 4];
#pragma unroll
                for (int kk = 0; kk < 4; kk++) {
                    float4 wv = *(const float4*)&wbuf[(kq * 4 + kk) * FPAD + ct * 4];
                    float2 wlo = make_float2(wv.x, wv.y), whi = make_float2(wv.z, wv.w);
#pragma unroll
                    for (int i = 0; i < 8; i++) {
                        float hk = (kk == 0) ? h4[i].x : (kk == 1) ? h4[i].y
                                 : (kk == 2) ? h4[i].z : h4[i].w;
                        float2 hh = make_float2(hk, hk);
                        acc2[i][0] = ffma2(wlo, hh, acc2[i][0]);
                        acc2[i][1] = ffma2(whi, hh, acc2[i][1]);
                    }
                }
            }
        }
        __syncthreads();
#pragma unroll
        for (int i = 0; i < 8; i++) {
            int w = wg * 8 + i;
            *(float4*)&wbuf[w * FPAD + ct * 4] =
                make_float4(acc2[i][0].x, acc2[i][0].y, acc2[i][1].x, acc2[i][1].y);
        }
        __syncthreads();
        {   // LSTM cell update (gate order i,f,g,o)
            int w = tid >> 4, u0 = (tid & 15) * 8;
            const float* gw = wbuf + w * FPAD;
            float* outp = out_all + ((size_t)t_eff * NW + wbase + w) * 256 + d * 128 + u0;
#pragma unroll
            for (int q = 0; q < 8; q++) {
                int u = u0 + q;
                float iv = gw[u], fv = gw[128 + u], gv = gw[256 + u], ov = gw[384 + u];
                float c = fsig(fv) * cs[w * 128 + u] + fsig(iv) * ftanh(gv);
                float h = fsig(ov) * ftanh(c);
                cs[w * 128 + u] = c; hs[w * 128 + u] = h;
                outp[q] = h;
            }
        }
    }
}

// ---------------- attention ----------------
__global__ void attn_dot(const float* __restrict__ energy, const float* __restrict__ wv,
                         float* __restrict__ e, int rows) {
    int r = blockIdx.x * 8 + (threadIdx.x >> 5);
    int lane = threadIdx.x & 31;
    if (r >= rows) return;
    const float* row = energy + (size_t)r * 256;
    float p = 0.f;
#pragma unroll
    for (int h = 0; h < 8; h++) p += row[lane + h * 32] * wv[lane + h * 32];
#pragma unroll
    for (int o = 16; o; o >>= 1) p += __shfl_xor_sync(0xffffffffu, p, o);
    if (!lane) e[r] = p;
}

__global__ void attn_ctx(const float* __restrict__ e, const float* __restrict__ out_all,
                         float* __restrict__ feat, int T, int off) {
    int w = blockIdx.x, h = threadIdx.x;  // 256
    __shared__ float a[16];
    if (h < T) a[h] = e[(size_t)h * NW + w];
    __syncthreads();
    if (h == 0) {
        float mx = -1e30f;
        for (int t = 0; t < T; t++) mx = fmaxf(mx, a[t]);
        float sd = 0.f;
        for (int t = 0; t < T; t++) { a[t] = __expf(a[t] - mx); sd += a[t]; }
        float inv = __fdividef(1.0f, sd);
        for (int t = 0; t < T; t++) a[t] *= inv;
    }
    __syncthreads();
    float c = 0.f;
    for (int t = 0; t < T; t++) c += a[t] * out_all[((size_t)t * NW + w) * 256 + h];
    feat[(size_t)w * 768 + off + h] = c;
}

// ---------------- word-level BiLSTM: 2 clusters of 4 CTAs, weights in registers ----------------
// Per-step cluster.sync (UCGABAR_WAIT ~490 + L1D flush) replaced by a DOUBLE-
// BUFFERED mbarrier handshake: mbar[s&1], count=128 (32 producers x 4 CTAs),
// wait parity flips every two steps ((s>>1)&1). Two barriers prevent a fast
// CTA's step-s+1 arrivals from being miscounted into a slow CTA's step-s phase.
#define WCL 4
__global__ void __cluster_dims__(WCL, 1, 1) __launch_bounds__(256, 1)
word_lstm_kernel(const float* __restrict__ pre,   // [NW][1024]
                 const float* __restrict__ Whh,   // [2][512][128]
                 float* __restrict__ y) {         // [NW][256]
    __shared__ float hbuf[2][128];
    __shared__ float gsum[128];
    __shared__ __align__(16) unsigned long long mbar[2];
    int tid = threadIdx.x;
    unsigned rank;
    asm("mov.u32 %0, %%cluster_ctarank;" : "=r"(rank));
    int dir = blockIdx.x >> 2;
    int row = tid >> 1;        // 0..127 local gate row
    int half = tid & 1;        // k-half
    int grow = (row >> 5) * 128 + (int)rank * 32 + (row & 31);   // global gate row

    float2 w2[32];
    {
        const float2* wp = (const float2*)(Whh + ((size_t)dir * 512 + grow) * 128 + half * 64);
#pragma unroll
        for (int i = 0; i < 32; i++) w2[i] = wp[i];
    }
    if (tid < 128) { hbuf[0][tid] = 0.f; hbuf[1][tid] = 0.f; }
    uint32_t mb0 = (uint32_t)__cvta_generic_to_shared(&mbar[0]);
    uint32_t mb1 = (uint32_t)__cvta_generic_to_shared(&mbar[1]);
    if (tid == 0) {
        asm volatile("mbarrier.init.shared.b64 [%0], %1;" :: "r"(mb0), "r"(32 * WCL) : "memory");
        asm volatile("mbarrier.init.shared.b64 [%0], %1;" :: "r"(mb1), "r"(32 * WCL) : "memory");
    }
    float cval = 0.f;
    __syncthreads();
    asm volatile("barrier.cluster.arrive.aligned;" ::: "memory");
    asm volatile("barrier.cluster.wait.aligned;" ::: "memory");

    const float* prep = pre + (size_t)(dir ? (NW - 1) : 0) * 1024 + dir * 512 + grow;
    long pstep = dir ? -1024 : 1024;
    float* yp = (tid < 32)
        ? y + (size_t)(dir ? (NW - 1) : 0) * 256 + dir * 128 + (int)rank * 32 + tid
        : y;
    long ystep = dir ? -256 : 256;
    uint32_t haddr0 = (uint32_t)__cvta_generic_to_shared(&hbuf[0][(int)rank * 32 + (tid & 31)]);
    uint32_t haddr1 = (uint32_t)__cvta_generic_to_shared(&hbuf[1][(int)rank * 32 + (tid & 31)]);
    // precompute remote addresses (mapa) for h slots and both mbarriers
    uint32_t rh0[WCL], rh1[WCL], rmb0[WCL], rmb1[WCL];
#pragma unroll
    for (int p = 0; p < WCL; p++) {
        asm("mapa.shared::cluster.u32 %0, %1, %2;" : "=r"(rh0[p]) : "r"(haddr0), "r"(p));
        asm("mapa.shared::cluster.u32 %0, %1, %2;" : "=r"(rh1[p]) : "r"(haddr1), "r"(p));
        asm("mapa.shared::cluster.u32 %0, %1, %2;" : "=r"(rmb0[p]) : "r"(mb0), "r"(p));
        asm("mapa.shared::cluster.u32 %0, %1, %2;" : "=r"(rmb1[p]) : "r"(mb1), "r"(p));
    }

    float pv = __ldg(prep);
    for (int s = 0; s < NW; s++) {
        int cur = s & 1;
        // only half==0 seeds with the input projection (avoid double count)
        float2 a0 = make_float2(half ? 0.f : pv, 0.f);
        float2 a1 = make_float2(0.f, 0.f);
        float2 a2v = make_float2(0.f, 0.f);
        float2 a3 = make_float2(0.f, 0.f);
        const float4* h4 = (const float4*)(&hbuf[cur][half * 64]);
#pragma unroll
        for (int i = 0; i < 16; i++) {
            float4 hv = h4[i];
            float2 p0 = make_float2(hv.x, hv.y), p1 = make_float2(hv.z, hv.w);
            if (i & 1) { a2v = ffma2(w2[2 * i], p0, a2v); a3 = ffma2(w2[2 * i + 1], p1, a3); }
            else       { a0  = ffma2(w2[2 * i], p0, a0);  a1 = ffma2(w2[2 * i + 1], p1, a1); }
        }
        if (s + 1 < NW) { prep += pstep; pv = __ldg(prep); }   // prefetch
        float acc = (a0.x + a0.y) + (a1.x + a1.y) + ((a2v.x + a2v.y) + (a3.x + a3.y));
        acc += __shfl_xor_sync(0xffffffffu, acc, 1);
        if (!half) gsum[row] = acc;
        __syncthreads();
        if (tid < 32) {
            float iv = gsum[tid], fv = gsum[32 + tid], gv = gsum[64 + tid], ov = gsum[96 + tid];
            cval = fsig(fv) * cval + fsig(iv) * ftanh(gv);
            float hv = fsig(ov) * ftanh(cval);
            *yp = hv;
            yp += ystep;
            // write h into the NEXT buffer of all 4 CTAs, then publish on mbar[cur]
#pragma unroll
            for (int p = 0; p < WCL; p++)
                asm volatile("st.shared::cluster.f32 [%0], %1;"
                             :: "r"(cur ? rh0[p] : rh1[p]), "f"(hv) : "memory");
            asm volatile("fence.acq_rel.cluster;" ::: "memory");
#pragma unroll
            for (int p = 0; p < WCL; p++)
                asm volatile("mbarrier.arrive.shared::cluster.b64 _, [%0];"
                             :: "r"(cur ? rmb1[p] : rmb0[p]) : "memory");
        }
        // wait for 128 arrivals on mbar[s&1]; parity flips every 2 steps
        {
            uint32_t mbw = cur ? mb1 : mb0;
            uint32_t par = (s >> 1) & 1;
            uint32_t done;
            asm volatile(
                "{\n\t.reg .pred p;\n\t"
                "mbarrier.try_wait.parity.acquire.cta.shared::cta.b64 p, [%1], %2;\n\t"
                "selp.b32 %0, 1, 0, p;\n\t}"
                : "=r"(done) : "r"(mbw), "r"(par) : "memory");
            if (!done) {
                asm volatile(
                    "{\n\t.reg .pred P1;\n\t"
                    "WLP%=:\n\t"
                    "mbarrier.try_wait.parity.acquire.cta.shared::cta.b64 P1, [%0], %1, 0x989680;\n\t"
                    "@P1 bra.uni WLD%=;\n\t"
                    "bra.uni WLP%=;\n\t"
                    "WLD%=:\n\t}"
                    :: "r"(mbw), "r"(par) : "memory");
            }
        }
        asm volatile("fence.acq_rel.cluster;" ::: "memory");
    }
    asm volatile("barrier.cluster.arrive.aligned;" ::: "memory");
    asm volatile("barrier.cluster.wait.aligned;" ::: "memory");
}

// ---------------- classifier + log_softmax ----------------
__global__ void classifier(const float* __restrict__ y,
                           const float* __restrict__ Wp, const float* __restrict__ bp,
                           const float* __restrict__ Wn, const float* __restrict__ bn,
                           float* __restrict__ out) {
    int w = blockIdx.x, j = threadIdx.x;  // 64 threads
    __shared__ float ys[256];
    __shared__ float l[64];
    __shared__ float red[4];
    for (int k = j; k < 256; k += 64) ys[k] = y[(size_t)w * 256 + k];
    __syncthreads();
    float v = 0.f;
    if (j < 47) {
        const float* Wr = Wp + (size_t)j * 256;
        float sacc = bp[j];
        for (int k = 0; k < 256; k++) sacc += ys[k] * Wr[k];
        v = sacc;
    } else if (j < 60) {
        const float* Wr = Wn + (size_t)(j - 47) * 256;
        float sacc = bn[j - 47];
        for (int k = 0; k < 256; k++) sacc += ys[k] * Wr[k];
        v = sacc;
    }
    l[j] = v;
    __syncthreads();
    if (j == 0) {
        float mx = -1e30f;
        for (int k = 0; k < 47; k++) mx = fmaxf(mx, l[k]);
        float sd = 0.f;
        for (int k = 0; k < 47; k++) sd += __expf(l[k] - mx);
        red[0] = mx; red[1] = __logf(sd);
    }
    if (j == 1) {
        float mx = -1e30f;
        for (int k = 47; k < 60; k++) mx = fmaxf(mx, l[k]);
        float sd = 0.f;
        for (int k = 47; k < 60; k++) sd += __expf(l[k] - mx);
        red[2] = mx; red[3] = __logf(sd);
    }
    __syncthreads();
    if (j < 47) out[(size_t)w * 47 + j] = l[j] - red[0] - red[1];
    else if (j < 60) out[(size_t)NW * 47 + (size_t)w * 13 + (j - 47)] = l[j] - red[2] - red[3];
}

// ---------------- launch ----------------
#define SYM(p, arr) do { void* _t = nullptr; cudaGetSymbolAddress(&_t, arr); p = (float*)_t; } while (0)
#define FUSED_SMEM (12352 * 4)

extern "C" void kernel_launch(void* const* d_in, const int* in_sizes, int n_in,
                              void* d_out, int out_size) {
    const int* word_ids = (const int*)d_in[0];
    const int* syl_ids  = (const int*)d_in[1];
    const int* char_ids = (const int*)d_in[2];
    const int* feat_ids = (const int*)d_in[3];
    const float* emb_char   = (const float*)d_in[4];
    const float* emb_syl    = (const float*)d_in[5];
    const float* emb_word   = (const float*)d_in[6];
    const float* emb_prefix = (const float*)d_in[7];
    const float* aW_c = (const float*)d_in[8];
    const float* ab_c = (const float*)d_in[9];
    const float* aw_c = (const float*)d_in[10];
    const float* aW_s = (const float*)d_in[11];
    const float* ab_s = (const float*)d_in[12];
    const float* aw_s = (const float*)d_in[13];
    const float* Wih_c = (const float*)d_in[14];
    const float* Whh_c = (const float*)d_in[15];
    const float* bih_c = (const float*)d_in[16];
    const float* bhh_c = (const float*)d_in[17];
    const float* Wih_s = (const float*)d_in[18];
    const float* Whh_s = (const float*)d_in[19];
    const float* bih_s = (const float*)d_in[20];
    const float* bhh_s = (const float*)d_in[21];
    const float* Wih_w = (const float*)d_in[22];
    const float* Whh_w = (const float*)d_in[23];
    const float* bih_w = (const float*)d_in[24];
    const float* bhh_w = (const float*)d_in[25];
    const float* W_pos = (const float*)d_in[26];
    const float* b_pos = (const float*)d_in[27];
    const float* W_ner = (const float*)d_in[28];
    const float* b_ner = (const float*)d_in[29];
    float* out = (float*)d_out;

    float *Xc, *Xs, *preC, *preS, *outC, *outS, *energy, *evec, *feat, *preW, *y;
    SYM(Xc, g_Xc); SYM(Xs, g_Xs); SYM(preC, g_preC); SYM(preS, g_preS);
    SYM(outC, g_outC); SYM(outS, g_outS); SYM(energy, g_energy); SYM(evec, g_e);
    SYM(feat, g_feat); SYM(preW, g_preW); SYM(y, g_y);

    cudaFuncSetAttribute(fused_lstm, cudaFuncAttributeMaxDynamicSharedMemorySize, FUSED_SMEM);

    // embedding gathers
    gather_x<<<dim3(NW, TCN), 64>>>(char_ids, emb_char, Xc, TCN);
    gather_x<<<dim3(NW, TSN), 64>>>(syl_ids, emb_syl, Xs, TSN);
    gather_word<<<NW, 256>>>(word_ids, emb_word, feat);

    // input projections (bias = bih + bhh folded in)
    gemm_abT<<<dim3(1024 / 64, (TCN * NW) / 64), 256>>>(Xc, Wih_c, preC, bih_c, bhh_c, TCN * NW, 1024, 64, 0);
    gemm_abT<<<dim3(1024 / 64, (TSN * NW) / 64), 256>>>(Xs, Wih_s, preS, bih_s, bhh_s, TSN * NW, 1024, 64, 0);

    // fused persistent char / syl BiLSTMs
    fused_lstm<<<dim3(NW / 16, 2), 256, FUSED_SMEM>>>(preC, Whh_c, feat_ids, emb_prefix, outC, TCN);
    fused_lstm<<<dim3(NW / 16, 2), 256, FUSED_SMEM>>>(preS, Whh_s, feat_ids, emb_prefix, outS, TSN);

    // char attention -> feat[:,256:512]
    gemm_abT<<<dim3(256 / 64, (TCN * NW) / 64), 256>>>(outC, aW_c, energy, ab_c, nullptr, TCN * NW, 256, 256, 1);
    attn_dot<<<(TCN * NW) / 8, 256>>>(energy, aw_c, evec, TCN * NW);
    attn_ctx<<<NW, 256>>>(evec, outC, feat, TCN, 256);

    // syl attention -> feat[:,512:768]
    gemm_abT<<<dim3(256 / 64, (TSN * NW) / 64), 256>>>(outS, aW_s, energy, ab_s, nullptr, TSN * NW, 256, 256, 1);
    attn_dot<<<(TSN * NW) / 8, 256>>>(energy, aw_s, evec, TSN * NW);
    attn_ctx<<<NW, 256>>>(evec, outS, feat, TSN, 512);

    // word input projection
    gemm_abT<<<dim3(1024 / 64, NW / 64), 256>>>(feat, Wih_w, preW, bih_w, bhh_w, NW, 1024, 768, 0);

    // sequential word BiLSTM (2 clusters of 4 CTAs, double-buffered mbarrier)
    word_lstm_kernel<<<2 * WCL, 256>>>(preW, Whh_w, y);

    // classifier + log_softmax
    classifier<<<NW, 64>>>(y, W_pos, b_pos, W_ner, b_ner, out);
}

// round 17
// speedup vs baseline: 1.1977x; 1.1977x over previous
#include <cuda_runtime.h>
#include <cstdint>
#include <string.h>
#include <math.h>

#define NW 2048
#define TCN 12
#define TSN 4

// ---------------- scratch (device globals; no allocation) ----------------
__device__ float g_Xc[TCN * NW * 64];
__device__ float g_Xs[TSN * NW * 64];
__device__ float g_preC[TCN * NW * 1024];      // [t][w][dir*512+gaterow]
__device__ float g_preS[TSN * NW * 1024];
__device__ float g_outC[TCN * NW * 256];       // [t][w][256]
__device__ float g_outS[TSN * NW * 256];
__device__ float g_energy[TCN * NW * 256];
__device__ float g_e[TCN * NW];
__device__ float g_feat[NW * 768];             // [w][word|char_ctx|syl_ctx]
__device__ float g_preW[NW * 1024];
__device__ float g_y[NW * 256];

__device__ __forceinline__ float fsig(float x) {
    return __fdividef(1.f, 1.f + __expf(-x));
}
__device__ __forceinline__ float ftanh(float x) {
    float e = __expf(2.f * x);
    return 1.f - __fdividef(2.f, e + 1.f);
}

// packed dual-fp32 FMA (sm_100+ FFMA2; ptxas never emits it from C++ — PTX only)
__device__ __forceinline__ float2 ffma2(float2 a, float2 b, float2 c) {
    unsigned long long ua, ub, uc;
    memcpy(&ua, &a, 8); memcpy(&ub, &b, 8); memcpy(&uc, &c, 8);
    asm("fma.rn.f32x2 %0, %1, %2, %0;" : "+l"(uc) : "l"(ua), "l"(ub));
    float2 d; memcpy(&d, &uc, 8);
    return d;
}

// ---------------- embedding gathers ----------------
__global__ void gather_x(const int* __restrict__ ids, const float* __restrict__ emb,
                         float* __restrict__ X, int T) {
    int w = blockIdx.x, t = blockIdx.y, j = threadIdx.x;  // 64 threads
    X[((size_t)t * NW + w) * 64 + j] = emb[(size_t)ids[w * T + t] * 64 + j];
}

__global__ void gather_word(const int* __restrict__ wid, const float* __restrict__ embw,
                            float* __restrict__ feat) {
    int w = blockIdx.x, j = threadIdx.x;  // 256
    feat[(size_t)w * 768 + j] = embw[(size_t)wid[w] * 256 + j];
}

// ---------------- GEMM: C[M,N] = A[M,K]*B[N,K]^T + b1 + b2 (opt tanh), FFMA2 ----------------
#define GPAD 20
__global__ __launch_bounds__(256) void gemm_abT(
    const float* __restrict__ A, const float* __restrict__ B, float* __restrict__ C,
    const float* __restrict__ b1, const float* __restrict__ b2,
    int M, int N, int K, int do_tanh) {
    __shared__ float As[64 * GPAD];
    __shared__ float Bs[64 * GPAD];
    int tid = threadIdx.x;
    int m0 = blockIdx.y * 64, n0 = blockIdx.x * 64;
    int lrow = tid >> 2, lk = (tid & 3) * 4;
    int tx = tid & 15, ty = tid >> 4;
    float2 acc2[4][4];
#pragma unroll
    for (int i = 0; i < 4; i++)
#pragma unroll
        for (int j = 0; j < 4; j++) acc2[i][j] = make_float2(0.f, 0.f);

    for (int k0 = 0; k0 < K; k0 += 16) {
        float4 a4 = *(const float4*)(A + (size_t)(m0 + lrow) * K + k0 + lk);
        float4 b4 = *(const float4*)(B + (size_t)(n0 + lrow) * K + k0 + lk);
        __syncthreads();
        *(float4*)&As[lrow * GPAD + lk] = a4;
        *(float4*)&Bs[lrow * GPAD + lk] = b4;
        __syncthreads();
#pragma unroll
        for (int kq = 0; kq < 16; kq += 4) {
            float4 av[4], bv[4];
#pragma unroll
            for (int i = 0; i < 4; i++) av[i] = *(const float4*)&As[(ty + 16 * i) * GPAD + kq];
#pragma unroll
            for (int j = 0; j < 4; j++) bv[j] = *(const float4*)&Bs[(tx + 16 * j) * GPAD + kq];
#pragma unroll
            for (int i = 0; i < 4; i++)
#pragma unroll
                for (int j = 0; j < 4; j++) {
                    acc2[i][j] = ffma2(make_float2(av[i].x, av[i].y),
                                       make_float2(bv[j].x, bv[j].y), acc2[i][j]);
                    acc2[i][j] = ffma2(make_float2(av[i].z, av[i].w),
                                       make_float2(bv[j].z, bv[j].w), acc2[i][j]);
                }
        }
    }
#pragma unroll
    for (int i = 0; i < 4; i++) {
        int m = m0 + ty + 16 * i;
#pragma unroll
        for (int j = 0; j < 4; j++) {
            int n = n0 + tx + 16 * j;
            float v = acc2[i][j].x + acc2[i][j].y;
            if (b1) v += b1[n];
            if (b2) v += b2[n];
            if (do_tanh) v = ftanh(v);
            C[(size_t)m * N + n] = v;
        }
    }
}

// ---------------- fused persistent char/syl BiLSTM ----------------
#define FPAD 516
// smem floats: hs 2048 + cs 2048 + wbuf 16*516 = 12352  (49,408 B, dynamic)
__global__ __launch_bounds__(256, 2) void fused_lstm(
    const float* __restrict__ pre,   // [T][NW][1024]
    const float* __restrict__ Whh,   // [2][512][128]
    const int* __restrict__ fid, const float* __restrict__ embp,
    float* __restrict__ out_all,     // [T][NW][256]
    int T) {
    extern __shared__ float sm[];
    float* hs = sm;                  // [16][128]
    float* cs = sm + 2048;           // [16][128]
    float* wbuf = sm + 4096;         // [16][FPAD] chunk (k-major); reused for gates
    int tid = threadIdx.x;
    int d = blockIdx.y;
    int wbase = blockIdx.x * 16;
    int wg = tid >> 7;               // word group 0/1 (8 words each)
    int ct = tid & 127;              // col-thread: owns gate cols ct*4..ct*4+3
    const float* Wb = Whh + (size_t)d * 512 * 128;

    {   // init h0 = prefix embedding slice, c0 = 0
        int w = tid >> 4, u0 = (tid & 15) * 8;
        const float* hp = embp + (size_t)fid[wbase + w] * 256 + d * 128 + u0;
#pragma unroll
        for (int q = 0; q < 8; q++) { hs[w * 128 + u0 + q] = hp[q]; cs[w * 128 + u0 + q] = 0.f; }
    }

    for (int t = 0; t < T; t++) {
        int t_eff = d ? (T - 1 - t) : t;
        const float* prow = pre + ((size_t)t_eff * NW + wbase) * 1024 + d * 512;
        float2 acc2[8][2];
#pragma unroll
        for (int i = 0; i < 8; i++) {
            float4 p = *(const float4*)(prow + (size_t)(wg * 8 + i) * 1024 + ct * 4);
            acc2[i][0] = make_float2(p.x, p.y);
            acc2[i][1] = make_float2(p.z, p.w);
        }

#pragma unroll 1
        for (int k0 = 0; k0 < 128; k0 += 16) {
            __syncthreads();
#pragma unroll
            for (int it = 0; it < 8; it++) {      // stage 512x16 Whh chunk, k-major
                int e = tid + 256 * it;
                int n = e >> 2, kq = e & 3;
                float4 v = *(const float4*)(Wb + (size_t)n * 128 + k0 + kq * 4);
                wbuf[(kq * 4 + 0) * FPAD + n] = v.x;
                wbuf[(kq * 4 + 1) * FPAD + n] = v.y;
                wbuf[(kq * 4 + 2) * FPAD + n] = v.z;
                wbuf[(kq * 4 + 3) * FPAD + n] = v.w;
            }
            __syncthreads();
#pragma unroll
            for (int kq = 0; kq < 4; kq++) {
                float4 h4[8];
#pragma unroll
                for (int i = 0; i < 8; i++)
                    h4[i] = *(const float4*)&hs[(wg * 8 + i) * 128 + k0 + kq * 4];
#pragma unroll
                for (int kk = 0; kk < 4; kk++) {
                    float4 wv = *(const float4*)&wbuf[(kq * 4 + kk) * FPAD + ct * 4];
                    float2 wlo = make_float2(wv.x, wv.y), whi = make_float2(wv.z, wv.w);
#pragma unroll
                    for (int i = 0; i < 8; i++) {
                        float hk = (kk == 0) ? h4[i].x : (kk == 1) ? h4[i].y
                                 : (kk == 2) ? h4[i].z : h4[i].w;
                        float2 hh = make_float2(hk, hk);
                        acc2[i][0] = ffma2(wlo, hh, acc2[i][0]);
                        acc2[i][1] = ffma2(whi, hh, acc2[i][1]);
                    }
                }
            }
        }
        __syncthreads();
#pragma unroll
        for (int i = 0; i < 8; i++) {
            int w = wg * 8 + i;
            *(float4*)&wbuf[w * FPAD + ct * 4] =
                make_float4(acc2[i][0].x, acc2[i][0].y, acc2[i][1].x, acc2[i][1].y);
        }
        __syncthreads();
        {   // LSTM cell update (gate order i,f,g,o)
            int w = tid >> 4, u0 = (tid & 15) * 8;
            const float* gw = wbuf + w * FPAD;
            float* outp = out_all + ((size_t)t_eff * NW + wbase + w) * 256 + d * 128 + u0;
#pragma unroll
            for (int q = 0; q < 8; q++) {
                int u = u0 + q;
                float iv = gw[u], fv = gw[128 + u], gv = gw[256 + u], ov = gw[384 + u];
                float c = fsig(fv) * cs[w * 128 + u] + fsig(iv) * ftanh(gv);
                float h = fsig(ov) * ftanh(c);
                cs[w * 128 + u] = c; hs[w * 128 + u] = h;
                outp[q] = h;
            }
        }
    }
}

// ---------------- attention ----------------
__global__ void attn_dot(const float* __restrict__ energy, const float* __restrict__ wv,
                         float* __restrict__ e, int rows) {
    int r = blockIdx.x * 8 + (threadIdx.x >> 5);
    int lane = threadIdx.x & 31;
    if (r >= rows) return;
    const float* row = energy + (size_t)r * 256;
    float p = 0.f;
#pragma unroll
    for (int h = 0; h < 8; h++) p += row[lane + h * 32] * wv[lane + h * 32];
#pragma unroll
    for (int o = 16; o; o >>= 1) p += __shfl_xor_sync(0xffffffffu, p, o);
    if (!lane) e[r] = p;
}

__global__ void attn_ctx(const float* __restrict__ e, const float* __restrict__ out_all,
                         float* __restrict__ feat, int T, int off) {
    int w = blockIdx.x, h = threadIdx.x;  // 256
    __shared__ float a[16];
    if (h < T) a[h] = e[(size_t)h * NW + w];
    __syncthreads();
    if (h == 0) {
        float mx = -1e30f;
        for (int t = 0; t < T; t++) mx = fmaxf(mx, a[t]);
        float sd = 0.f;
        for (int t = 0; t < T; t++) { a[t] = __expf(a[t] - mx); sd += a[t]; }
        float inv = __fdividef(1.0f, sd);
        for (int t = 0; t < T; t++) a[t] *= inv;
    }
    __syncthreads();
    float c = 0.f;
    for (int t = 0; t < T; t++) c += a[t] * out_all[((size_t)t * NW + w) * 256 + h];
    feat[(size_t)w * 768 + off + h] = c;
}

// ---------------- word-level BiLSTM: 2 clusters of 4 CTAs ----------------
// Fence-free sync (R13 showed cluster fences cost ~+450us): seq-tagged slots.
// Each producer writes ONE aligned 8B packet {h, seq} per peer via
// st.shared::cluster.b64 (single-copy atomic: payload+flag land together).
// Consumers spin on the seq word in LOCAL smem (DSMEM stores land in physical
// smem; no fence needed), then __syncthreads. Slots double-buffered; s vs s+2
// overwrite ordered transitively (publish happens after the CTA-local barrier
// that follows all reads of that buffer).
#define WCL 4
__global__ void __cluster_dims__(WCL, 1, 1) __launch_bounds__(256, 1)
word_lstm_kernel(const float* __restrict__ pre,   // [NW][1024]
                 const float* __restrict__ Whh,   // [2][512][128]
                 float* __restrict__ y) {         // [NW][256]
    __shared__ __align__(16) float2 hseq[2][128];   // {h, seq_bits}
    __shared__ float gsum[128];
    int tid = threadIdx.x;
    unsigned rank;
    asm("mov.u32 %0, %%cluster_ctarank;" : "=r"(rank));
    int dir = blockIdx.x >> 2;
    int row = tid >> 1;        // 0..127 local gate row
    int half = tid & 1;        // k-half
    int grow = (row >> 5) * 128 + (int)rank * 32 + (row & 31);   // global gate row

    float2 w2[32];
    {
        const float2* wp = (const float2*)(Whh + ((size_t)dir * 512 + grow) * 128 + half * 64);
#pragma unroll
        for (int i = 0; i < 32; i++) w2[i] = wp[i];
    }
    if (tid < 128) {
        hseq[0][tid] = make_float2(0.f, __int_as_float(0));    // h(0)=0, ready for s=0
        hseq[1][tid] = make_float2(0.f, __int_as_float(-1));   // not ready
    }
    float cval = 0.f;
    __syncthreads();
    // all CTAs' slot init must complete before any remote publish can land
    asm volatile("barrier.cluster.arrive.aligned;" ::: "memory");
    asm volatile("barrier.cluster.wait.aligned;" ::: "memory");

    const float* prep = pre + (size_t)(dir ? (NW - 1) : 0) * 1024 + dir * 512 + grow;
    long pstep = dir ? -1024 : 1024;
    float* yp = (tid < 32)
        ? y + (size_t)(dir ? (NW - 1) : 0) * 256 + dir * 128 + (int)rank * 32 + tid
        : y;
    long ystep = dir ? -256 : 256;
    // remote slot addresses for this producer's slot in both buffers, all peers
    uint32_t s0 = (uint32_t)__cvta_generic_to_shared(&hseq[0][(int)rank * 32 + (tid & 31)]);
    uint32_t s1 = (uint32_t)__cvta_generic_to_shared(&hseq[1][(int)rank * 32 + (tid & 31)]);
    uint32_t rs0[WCL], rs1[WCL];
#pragma unroll
    for (int p = 0; p < WCL; p++) {
        asm("mapa.shared::cluster.u32 %0, %1, %2;" : "=r"(rs0[p]) : "r"(s0), "r"(p));
        asm("mapa.shared::cluster.u32 %0, %1, %2;" : "=r"(rs1[p]) : "r"(s1), "r"(p));
    }
    volatile int* seq0 = (volatile int*)((char*)&hseq[0][tid & 127] + 4);
    volatile int* seq1 = (volatile int*)((char*)&hseq[1][tid & 127] + 4);

    float pv = __ldg(prep);
    for (int s = 0; s < NW; s++) {
        int cur = s & 1;
        // wait until this thread's assigned slot carries step-s h
        if (tid < 128) {
            volatile int* sq = cur ? seq1 : seq0;
            while (*sq != s) { }
        }
        __syncthreads();
        // dot: h interleaved {h,seq} -> float4 gives 2 h values (.x,.z)
        float2 a0 = make_float2(half ? 0.f : pv, 0.f);
        float2 a1 = make_float2(0.f, 0.f);
        float2 a2v = make_float2(0.f, 0.f);
        float2 a3 = make_float2(0.f, 0.f);
        const float4* h4 = (const float4*)&hseq[cur][half * 64];
#pragma unroll
        for (int i = 0; i < 32; i++) {
            float4 q = h4[i];
            float2 hh = make_float2(q.x, q.z);
            int sel = i & 3;
            if (sel == 0)      a0  = ffma2(w2[i], hh, a0);
            else if (sel == 1) a1  = ffma2(w2[i], hh, a1);
            else if (sel == 2) a2v = ffma2(w2[i], hh, a2v);
            else               a3  = ffma2(w2[i], hh, a3);
        }
        if (s + 1 < NW) { prep += pstep; pv = __ldg(prep); }   // prefetch
        float acc = (a0.x + a0.y) + (a1.x + a1.y) + ((a2v.x + a2v.y) + (a3.x + a3.y));
        acc += __shfl_xor_sync(0xffffffffu, acc, 1);
        if (!half) gsum[row] = acc;
        __syncthreads();
        if (tid < 32) {
            float iv = gsum[tid], fv = gsum[32 + tid], gv = gsum[64 + tid], ov = gsum[96 + tid];
            cval = fsig(fv) * cval + fsig(iv) * ftanh(gv);
            float hv = fsig(ov) * ftanh(cval);
            // publish FIRST (critical path): one 8B packet {h, s+1} per peer
            unsigned long long pkt;
            float2 t2 = make_float2(hv, __int_as_float(s + 1));
            memcpy(&pkt, &t2, 8);
#pragma unroll
            for (int p = 0; p < WCL; p++)
                asm volatile("st.shared::cluster.b64 [%0], %1;"
                             :: "r"(cur ? rs0[p] : rs1[p]), "l"(pkt) : "memory");
            *yp = hv;
            yp += ystep;
        }
        // no barrier here: next iteration's poll + syncthreads is the join
    }
    asm volatile("barrier.cluster.arrive.aligned;" ::: "memory");
    asm volatile("barrier.cluster.wait.aligned;" ::: "memory");
}

// ---------------- classifier + log_softmax ----------------
__global__ void classifier(const float* __restrict__ y,
                           const float* __restrict__ Wp, const float* __restrict__ bp,
                           const float* __restrict__ Wn, const float* __restrict__ bn,
                           float* __restrict__ out) {
    int w = blockIdx.x, j = threadIdx.x;  // 64 threads
    __shared__ float ys[256];
    __shared__ float l[64];
    __shared__ float red[4];
    for (int k = j; k < 256; k += 64) ys[k] = y[(size_t)w * 256 + k];
    __syncthreads();
    float v = 0.f;
    if (j < 47) {
        const float* Wr = Wp + (size_t)j * 256;
        float sacc = bp[j];
        for (int k = 0; k < 256; k++) sacc += ys[k] * Wr[k];
        v = sacc;
    } else if (j < 60) {
        const float* Wr = Wn + (size_t)(j - 47) * 256;
        float sacc = bn[j - 47];
        for (int k = 0; k < 256; k++) sacc += ys[k] * Wr[k];
        v = sacc;
    }
    l[j] = v;
    __syncthreads();
    if (j == 0) {
        float mx = -1e30f;
        for (int k = 0; k < 47; k++) mx = fmaxf(mx, l[k]);
        float sd = 0.f;
        for (int k = 0; k < 47; k++) sd += __expf(l[k] - mx);
        red[0] = mx; red[1] = __logf(sd);
    }
    if (j == 1) {
        float mx = -1e30f;
        for (int k = 47; k < 60; k++) mx = fmaxf(mx, l[k]);
        float sd = 0.f;
        for (int k = 47; k < 60; k++) sd += __expf(l[k] - mx);
        red[2] = mx; red[3] = __logf(sd);
    }
    __syncthreads();
    if (j < 47) out[(size_t)w * 47 + j] = l[j] - red[0] - red[1];
    else if (j < 60) out[(size_t)NW * 47 + (size_t)w * 13 + (j - 47)] = l[j] - red[2] - red[3];
}

// ---------------- launch ----------------
#define SYM(p, arr) do { void* _t = nullptr; cudaGetSymbolAddress(&_t, arr); p = (float*)_t; } while (0)
#define FUSED_SMEM (12352 * 4)

extern "C" void kernel_launch(void* const* d_in, const int* in_sizes, int n_in,
                              void* d_out, int out_size) {
    const int* word_ids = (const int*)d_in[0];
    const int* syl_ids  = (const int*)d_in[1];
    const int* char_ids = (const int*)d_in[2];
    const int* feat_ids = (const int*)d_in[3];
    const float* emb_char   = (const float*)d_in[4];
    const float* emb_syl    = (const float*)d_in[5];
    const float* emb_word   = (const float*)d_in[6];
    const float* emb_prefix = (const float*)d_in[7];
    const float* aW_c = (const float*)d_in[8];
    const float* ab_c = (const float*)d_in[9];
    const float* aw_c = (const float*)d_in[10];
    const float* aW_s = (const float*)d_in[11];
    const float* ab_s = (const float*)d_in[12];
    const float* aw_s = (const float*)d_in[13];
    const float* Wih_c = (const float*)d_in[14];
    const float* Whh_c = (const float*)d_in[15];
    const float* bih_c = (const float*)d_in[16];
    const float* bhh_c = (const float*)d_in[17];
    const float* Wih_s = (const float*)d_in[18];
    const float* Whh_s = (const float*)d_in[19];
    const float* bih_s = (const float*)d_in[20];
    const float* bhh_s = (const float*)d_in[21];
    const float* Wih_w = (const float*)d_in[22];
    const float* Whh_w = (const float*)d_in[23];
    const float* bih_w = (const float*)d_in[24];
    const float* bhh_w = (const float*)d_in[25];
    const float* W_pos = (const float*)d_in[26];
    const float* b_pos = (const float*)d_in[27];
    const float* W_ner = (const float*)d_in[28];
    const float* b_ner = (const float*)d_in[29];
    float* out = (float*)d_out;

    float *Xc, *Xs, *preC, *preS, *outC, *outS, *energy, *evec, *feat, *preW, *y;
    SYM(Xc, g_Xc); SYM(Xs, g_Xs); SYM(preC, g_preC); SYM(preS, g_preS);
    SYM(outC, g_outC); SYM(outS, g_outS); SYM(energy, g_energy); SYM(evec, g_e);
    SYM(feat, g_feat); SYM(preW, g_preW); SYM(y, g_y);

    cudaFuncSetAttribute(fused_lstm, cudaFuncAttributeMaxDynamicSharedMemorySize, FUSED_SMEM);

    // embedding gathers
    gather_x<<<dim3(NW, TCN), 64>>>(char_ids, emb_char, Xc, TCN);
    gather_x<<<dim3(NW, TSN), 64>>>(syl_ids, emb_syl, Xs, TSN);
    gather_word<<<NW, 256>>>(word_ids, emb_word, feat);

    // input projections (bias = bih + bhh folded in)
    gemm_abT<<<dim3(1024 / 64, (TCN * NW) / 64), 256>>>(Xc, Wih_c, preC, bih_c, bhh_c, TCN * NW, 1024, 64, 0);
    gemm_abT<<<dim3(1024 / 64, (TSN * NW) / 64), 256>>>(Xs, Wih_s, preS, bih_s, bhh_s, TSN * NW, 1024, 64, 0);

    // fused persistent char / syl BiLSTMs
    fused_lstm<<<dim3(NW / 16, 2), 256, FUSED_SMEM>>>(preC, Whh_c, feat_ids, emb_prefix, outC, TCN);
    fused_lstm<<<dim3(NW / 16, 2), 256, FUSED_SMEM>>>(preS, Whh_s, feat_ids, emb_prefix, outS, TSN);

    // char attention -> feat[:,256:512]
    gemm_abT<<<dim3(256 / 64, (TCN * NW) / 64), 256>>>(outC, aW_c, energy, ab_c, nullptr, TCN * NW, 256, 256, 1);
    attn_dot<<<(TCN * NW) / 8, 256>>>(energy, aw_c, evec, TCN * NW);
    attn_ctx<<<NW, 256>>>(evec, outC, feat, TCN, 256);

    // syl attention -> feat[:,512:768]
    gemm_abT<<<dim3(256 / 64, (TSN * NW) / 64), 256>>>(outS, aW_s, energy, ab_s, nullptr, TSN * NW, 256, 256, 1);
    attn_dot<<<(TSN * NW) / 8, 256>>>(energy, aw_s, evec, TSN * NW);
    attn_ctx<<<NW, 256>>>(evec, outS, feat, TSN, 512);

    // word input projection
    gemm_abT<<<dim3(1024 / 64, NW / 64), 256>>>(feat, Wih_w, preW, bih_w, bhh_w, NW, 1024, 768, 0);

    // sequential word BiLSTM (2 clusters of 4 CTAs, fence-free seq-slot sync)
    word_lstm_kernel<<<2 * WCL, 256>>>(preW, Whh_w, y);

    // classifier + log_softmax
    classifier<<<NW, 64>>>(y, W_pos, b_pos, W_ner, b_ner, out);
}